// round 2
// baseline (speedup 1.0000x reference)
#include <cuda_runtime.h>
#include <cstdint>
#include <math.h>

#define BB 2
#define SS 2048
#define DD 2048
#define HH 16
#define DH 128

// fp32 scratch for Q,K,V in (b,h,s,dh) layout
__device__ float g_q[BB*HH*SS*DH];
__device__ float g_k[BB*HH*SS*DH];
__device__ float g_v[BB*HH*SS*DH];

__device__ __forceinline__ uint32_t f2tf(float f) {
    uint32_t r;
    asm("cvt.rna.tf32.f32 %0, %1;" : "=r"(r) : "f"(f));
    return r;
}

__device__ __forceinline__ void mma8(float* c, const uint32_t* a, uint32_t b0, uint32_t b1) {
    asm volatile(
        "mma.sync.aligned.m16n8k8.row.col.f32.tf32.tf32.f32 "
        "{%0,%1,%2,%3}, {%4,%5,%6,%7}, {%8,%9}, {%0,%1,%2,%3};\n"
        : "+f"(c[0]), "+f"(c[1]), "+f"(c[2]), "+f"(c[3])
        : "r"(a[0]), "r"(a[1]), "r"(a[2]), "r"(a[3]), "r"(b0), "r"(b1));
}

// ===================== Projection GEMM (+ fused RoPE) =====================
// C[token, o] = sum_k x[token,k] * w[o,k];  block tile 128x128, BK=32, tf32 mma.
// grid: (N/128=16, M/128=32, 3[q,k,v])
__global__ __launch_bounds__(256, 2) void proj_kernel(
    const float* __restrict__ x, const float* __restrict__ wq,
    const float* __restrict__ wk, const float* __restrict__ wv,
    const float* __restrict__ rcos, const float* __restrict__ rsin)
{
    __shared__ uint32_t As[128][36];  // stride 36: banks = (4*row + col) % 32, conflict-free
    __shared__ uint32_t Bs[128][36];

    const int z = blockIdx.z;
    const float* w = (z == 0) ? wq : (z == 1) ? wk : wv;
    float* outp = (z == 0) ? g_q : (z == 1) ? g_k : g_v;
    const bool rope = (z < 2);

    const int tid = threadIdx.x, lane = tid & 31, wid = tid >> 5;
    const int wm = wid >> 1, wn = wid & 1;
    const int m0 = blockIdx.y * 128, n0 = blockIdx.x * 128;
    const int g = lane >> 2, qd = lane & 3;

    float acc[2][8][4];
#pragma unroll
    for (int mi = 0; mi < 2; mi++)
#pragma unroll
        for (int nf = 0; nf < 8; nf++)
#pragma unroll
            for (int e = 0; e < 4; e++) acc[mi][nf][e] = 0.f;

    const int lr = tid >> 3;          // 0..31
    const int lc = (tid & 7) * 4;     // 0..28

    for (int k0 = 0; k0 < DD; k0 += 32) {
        __syncthreads();
#pragma unroll
        for (int p = 0; p < 4; p++) {
            int r = lr + 32 * p;
            float4 va = *(const float4*)(x + (m0 + r) * DD + k0 + lc);
            As[r][lc + 0] = f2tf(va.x); As[r][lc + 1] = f2tf(va.y);
            As[r][lc + 2] = f2tf(va.z); As[r][lc + 3] = f2tf(va.w);
            float4 vb = *(const float4*)(w + (n0 + r) * DD + k0 + lc);
            Bs[r][lc + 0] = f2tf(vb.x); Bs[r][lc + 1] = f2tf(vb.y);
            Bs[r][lc + 2] = f2tf(vb.z); Bs[r][lc + 3] = f2tf(vb.w);
        }
        __syncthreads();
#pragma unroll
        for (int ks = 0; ks < 4; ks++) {
            const int kk = ks * 8;
            uint32_t a[2][4];
#pragma unroll
            for (int mi = 0; mi < 2; mi++) {
                int row = wm * 32 + mi * 16 + g;
                a[mi][0] = As[row][kk + qd];
                a[mi][1] = As[row + 8][kk + qd];
                a[mi][2] = As[row][kk + qd + 4];
                a[mi][3] = As[row + 8][kk + qd + 4];
            }
#pragma unroll
            for (int nf = 0; nf < 8; nf++) {
                int col = wn * 64 + nf * 8 + g;
                uint32_t b0 = Bs[col][kk + qd];
                uint32_t b1 = Bs[col][kk + qd + 4];
                mma8(acc[0][nf], a[0], b0, b1);
                mma8(acc[1][nf], a[1], b0, b1);
            }
        }
    }

    // Epilogue: RoPE (fp32, register-local pairs) + store to (b,h,s,dh)
#pragma unroll
    for (int mi = 0; mi < 2; mi++) {
#pragma unroll
        for (int hh = 0; hh < 2; hh++) {
            int row = m0 + wm * 32 + mi * 16 + g + hh * 8;   // token id
            int b = row >> 11;          // /S
            int s = row & (SS - 1);
#pragma unroll
            for (int nf = 0; nf < 8; nf++) {
                int col = n0 + wn * 64 + nf * 8 + qd * 2;    // even
                int h = col >> 7, dh = col & 127;
                float v0 = acc[mi][nf][hh * 2 + 0];
                float v1 = acc[mi][nf][hh * 2 + 1];
                if (rope) {
                    float c = rcos[s * DH + dh];
                    float sn = rsin[s * DH + dh];
                    float r0 = v0 * c - v1 * sn;
                    float r1 = v1 * c + v0 * sn;
                    v0 = r0; v1 = r1;
                }
                float2* dst = (float2*)(outp + ((b * HH + h) * SS + s) * DH + dh);
                *dst = make_float2(v0, v1);
            }
        }
    }
}

// ===================== Flash attention + final Dh softmax =====================
#define QS_STR 132
#define KS_STR 132
#define VS_STR 136
#define PS_STR 68
#define OFF_Q 0
#define OFF_K (128 * QS_STR)
#define OFF_V (OFF_K + 64 * KS_STR)
#define OFF_P (OFF_V + 64 * VS_STR)
#define SMEM_FLOATS (OFF_P + 128 * PS_STR)
#define SMEM_BYTES (SMEM_FLOATS * 4)

__global__ __launch_bounds__(256, 1) void flash_kernel(float* __restrict__ out)
{
    extern __shared__ uint32_t sm[];
    uint32_t* Qs = sm + OFF_Q;
    uint32_t* Ks = sm + OFF_K;
    uint32_t* Vs = sm + OFF_V;
    uint32_t* Ps = sm + OFF_P;

    const int tid = threadIdx.x, lane = tid & 31, wid = tid >> 5;
    const int bh = blockIdx.y;
    const int qt = gridDim.x - 1 - blockIdx.x;   // big tiles launch first
    const int q0 = qt * 128;
    const int g = lane >> 2, qd = lane & 3;
    const int rw0 = q0 + wid * 16;
    const float e2 = (float)(1.4426950408889634 / 11.313708498984761); // log2(e)/sqrt(128)

    // stage Q tile (128 x 128)
#pragma unroll
    for (int i = 0; i < 16; i++) {
        int idx = tid + 256 * i;
        int r = idx >> 5;
        int c4 = (idx & 31) * 4;
        float4 v = *(const float4*)(g_q + (bh * SS + q0 + r) * DH + c4);
        uint32_t* dst = Qs + r * QS_STR + c4;
        dst[0] = f2tf(v.x); dst[1] = f2tf(v.y); dst[2] = f2tf(v.z); dst[3] = f2tf(v.w);
    }

    float oacc[16][4];
#pragma unroll
    for (int nf = 0; nf < 16; nf++)
#pragma unroll
        for (int e = 0; e < 4; e++) oacc[nf][e] = 0.f;
    float m2[2] = {-INFINITY, -INFINITY};
    float lsum[2] = {0.f, 0.f};

    const int ntiles = qt * 2 + 2;
    for (int t = 0; t < ntiles; t++) {
        const int k0g = t * 64;
        __syncthreads();
        // stage K,V tiles (64 x 128)
#pragma unroll
        for (int i = 0; i < 8; i++) {
            int idx = tid + 256 * i;
            int r = idx >> 5;
            int c4 = (idx & 31) * 4;
            float4 vk = *(const float4*)(g_k + (bh * SS + k0g + r) * DH + c4);
            uint32_t* dk = Ks + r * KS_STR + c4;
            dk[0] = f2tf(vk.x); dk[1] = f2tf(vk.y); dk[2] = f2tf(vk.z); dk[3] = f2tf(vk.w);
            float4 vv = *(const float4*)(g_v + (bh * SS + k0g + r) * DH + c4);
            uint32_t* dv = Vs + r * VS_STR + c4;
            dv[0] = f2tf(vv.x); dv[1] = f2tf(vv.y); dv[2] = f2tf(vv.z); dv[3] = f2tf(vv.w);
        }
        __syncthreads();

        const bool active = (k0g <= rw0 + 15);
        if (active) {
            float sacc[8][4];
#pragma unroll
            for (int nf = 0; nf < 8; nf++)
#pragma unroll
                for (int e = 0; e < 4; e++) sacc[nf][e] = 0.f;

            // S = Q K^T (k-dim = Dh = 128 -> 16 ksteps)
#pragma unroll
            for (int kd = 0; kd < 16; kd++) {
                const int kk = kd * 8;
                uint32_t a[4];
                int qrow = wid * 16 + g;
                a[0] = Qs[qrow * QS_STR + kk + qd];
                a[1] = Qs[(qrow + 8) * QS_STR + kk + qd];
                a[2] = Qs[qrow * QS_STR + kk + qd + 4];
                a[3] = Qs[(qrow + 8) * QS_STR + kk + qd + 4];
#pragma unroll
                for (int nf = 0; nf < 8; nf++) {
                    int krow = nf * 8 + g;
                    uint32_t b0 = Ks[krow * KS_STR + kk + qd];
                    uint32_t b1 = Ks[krow * KS_STR + kk + qd + 4];
                    mma8(sacc[nf], a, b0, b1);
                }
            }

            const bool needmask = (k0g + 63 > rw0);
            // online softmax per row-half; scale folded into log2 domain
#pragma unroll
            for (int hh = 0; hh < 2; hh++) {
                int rg = rw0 + g + hh * 8;
                float rmax = -INFINITY;
#pragma unroll
                for (int nf = 0; nf < 8; nf++) {
#pragma unroll
                    for (int e = 0; e < 2; e++) {
                        int col = k0g + nf * 8 + qd * 2 + e;
                        float sv = sacc[nf][hh * 2 + e] * e2;
                        if (needmask && col > rg) sv = -1e30f;
                        sacc[nf][hh * 2 + e] = sv;
                        rmax = fmaxf(rmax, sv);
                    }
                }
                rmax = fmaxf(rmax, __shfl_xor_sync(0xffffffffu, rmax, 1));
                rmax = fmaxf(rmax, __shfl_xor_sync(0xffffffffu, rmax, 2));
                float mnew = fmaxf(m2[hh], rmax);
                float corr = exp2f(m2[hh] - mnew);
                m2[hh] = mnew;
                float psum = 0.f;
#pragma unroll
                for (int nf = 0; nf < 8; nf++) {
#pragma unroll
                    for (int e = 0; e < 2; e++) {
                        float p = exp2f(sacc[nf][hh * 2 + e] - mnew);
                        psum += p;
                        sacc[nf][hh * 2 + e] = __uint_as_float(f2tf(p));
                    }
                }
                psum += __shfl_xor_sync(0xffffffffu, psum, 1);
                psum += __shfl_xor_sync(0xffffffffu, psum, 2);
                lsum[hh] = lsum[hh] * corr + psum;
#pragma unroll
                for (int nf = 0; nf < 16; nf++) {
                    oacc[nf][hh * 2 + 0] *= corr;
                    oacc[nf][hh * 2 + 1] *= corr;
                }
                // write P (tf32 bits) for this row-half
                int prow = wid * 16 + g + hh * 8;
#pragma unroll
                for (int nf = 0; nf < 8; nf++) {
                    Ps[prow * PS_STR + nf * 8 + qd * 2 + 0] = __float_as_uint(sacc[nf][hh * 2 + 0]);
                    Ps[prow * PS_STR + nf * 8 + qd * 2 + 1] = __float_as_uint(sacc[nf][hh * 2 + 1]);
                }
            }
            __syncwarp();

            // O += P V  (k-dim = kv = 64 -> 8 ksteps, n = Dh = 128 -> 16 n-frags)
#pragma unroll
            for (int j = 0; j < 8; j++) {
                uint32_t a[4];
                int prow = wid * 16 + g;
                a[0] = Ps[prow * PS_STR + j * 8 + qd];
                a[1] = Ps[(prow + 8) * PS_STR + j * 8 + qd];
                a[2] = Ps[prow * PS_STR + j * 8 + qd + 4];
                a[3] = Ps[(prow + 8) * PS_STR + j * 8 + qd + 4];
#pragma unroll
                for (int nf = 0; nf < 16; nf++) {
                    uint32_t b0 = Vs[(j * 8 + qd) * VS_STR + nf * 8 + g];
                    uint32_t b1 = Vs[(j * 8 + qd + 4) * VS_STR + nf * 8 + g];
                    mma8(oacc[nf], a, b0, b1);
                }
            }
        }
    }

    // Epilogue: O /= l, then softmax over Dh=128 (quad holds a full row), write fp32
    const int b = bh >> 4, h = bh & 15;
#pragma unroll
    for (int hh = 0; hh < 2; hh++) {
        int srow = rw0 + g + hh * 8;
        float inv = 1.0f / lsum[hh];
        float vals[32];
        float mx = -INFINITY;
#pragma unroll
        for (int nf = 0; nf < 16; nf++) {
            vals[nf * 2 + 0] = oacc[nf][hh * 2 + 0] * inv;
            vals[nf * 2 + 1] = oacc[nf][hh * 2 + 1] * inv;
            mx = fmaxf(mx, fmaxf(vals[nf * 2], vals[nf * 2 + 1]));
        }
        mx = fmaxf(mx, __shfl_xor_sync(0xffffffffu, mx, 1));
        mx = fmaxf(mx, __shfl_xor_sync(0xffffffffu, mx, 2));
        float ssum = 0.f;
#pragma unroll
        for (int i2 = 0; i2 < 32; i2++) {
            vals[i2] = expf(vals[i2] - mx);
            ssum += vals[i2];
        }
        ssum += __shfl_xor_sync(0xffffffffu, ssum, 1);
        ssum += __shfl_xor_sync(0xffffffffu, ssum, 2);
        float rinv = 1.0f / ssum;
#pragma unroll
        for (int nf = 0; nf < 16; nf++) {
            int col = h * 128 + nf * 8 + qd * 2;
            float2* dst = (float2*)(out + (b * SS + srow) * DD + col);
            *dst = make_float2(vals[nf * 2] * rinv, vals[nf * 2 + 1] * rinv);
        }
    }
}

extern "C" void kernel_launch(void* const* d_in, const int* in_sizes, int n_in,
                              void* d_out, int out_size)
{
    const float* x    = (const float*)d_in[0];
    const float* wq   = (const float*)d_in[1];
    const float* wk   = (const float*)d_in[2];
    const float* wv   = (const float*)d_in[3];
    const float* rcos = (const float*)d_in[4];
    const float* rsin = (const float*)d_in[5];
    float* out = (float*)d_out;

    static bool attr_set = false;
    // Idempotent, not a stream op; safe under graph capture. Called every time
    // would also be fine, but keep it cheap.
    if (!attr_set) {
        cudaFuncSetAttribute(flash_kernel, cudaFuncAttributeMaxDynamicSharedMemorySize, SMEM_BYTES);
        attr_set = true;
    }

    proj_kernel<<<dim3(16, 32, 3), 256>>>(x, wq, wk, wv, rcos, rsin);
    flash_kernel<<<dim3(16, BB * HH), 256, SMEM_BYTES>>>(out);
}